// round 7
// baseline (speedup 1.0000x reference)
#include <cuda_runtime.h>

#define N_NODES   100000
#define N_EDGES   1600000
#define NUM_GRAPHS 1000
#define HID 64
#define EPS 1e-5f

// ---------------- device scratch (no runtime allocation allowed) ----------------
__device__ float g_h[N_NODES * HID];        // current node features
__device__ float g_htmp[N_NODES * HID];     // relu(update) before BN
__device__ float g_agg[N_NODES * HID];      // raw scatter-add of relu(messages)
__device__ float g_graph[NUM_GRAPHS * HID]; // pooled graph features
__device__ int   g_deg[N_NODES];            // in-degree (dst counts)
__device__ float g_msgW[3][80 * 64];        // folded message weights (e-embed folded in)
__device__ float g_msgB[3][64];             // folded message bias
__device__ float g_stats[256];              // [0:64] msg sum, [64:128] msg sq, [128:192] upd sum, [192:256] upd sq

// vectorized global reduction (sm_90+)
__device__ __forceinline__ void red_add_v4(float* p, float a, float b, float c, float d) {
    asm volatile("red.global.add.v4.f32 [%0], {%1,%2,%3,%4};"
                 :: "l"(p), "f"(a), "f"(b), "f"(c), "f"(d) : "memory");
}

// ---------------- in-degree ----------------
__global__ void deg_kernel(const int* __restrict__ dst) {
    int i = blockIdx.x * blockDim.x + threadIdx.x;
    if (i < N_EDGES) atomicAdd(&g_deg[dst[i]], 1);
}

// ---------------- node embedding: h = x @ node_W + node_b ----------------
__global__ void __launch_bounds__(256) node_embed_kernel(const float* __restrict__ x,
                                                         const float* __restrict__ W,
                                                         const float* __restrict__ b) {
    __shared__ float sW[32 * 64];     // 8KB
    __shared__ float sIn[64 * 36];    // padded stride 36
    int tid = threadIdx.x;
    int n0 = blockIdx.x * 64;

    for (int i = tid; i < 512; i += 256) ((float4*)sW)[i] = ((const float4*)W)[i];
    for (int i = tid; i < 512; i += 256) {
        int r = i >> 3, p = i & 7;
        int node = n0 + r;
        float4 v = make_float4(0.f, 0.f, 0.f, 0.f);
        if (node < N_NODES) v = ((const float4*)x)[node * 8 + p];
        *(float4*)&sIn[r * 36 + p * 4] = v;
    }
    __syncthreads();

    int r = tid >> 2, cg = (tid & 3) << 4;
    float acc[16];
#pragma unroll
    for (int j = 0; j < 16; j++) acc[j] = b[cg + j];
#pragma unroll 8
    for (int k = 0; k < 32; k++) {
        float a = sIn[r * 36 + k];
#pragma unroll
        for (int j4 = 0; j4 < 4; j4++) {
            float4 w = *(float4*)&sW[k * 64 + cg + (j4 << 2)];
            acc[j4 * 4 + 0] += a * w.x;
            acc[j4 * 4 + 1] += a * w.y;
            acc[j4 * 4 + 2] += a * w.z;
            acc[j4 * 4 + 3] += a * w.w;
        }
    }
    int node = n0 + r;
    if (node < N_NODES) {
#pragma unroll
        for (int j4 = 0; j4 < 4; j4++)
            *(float4*)&g_h[node * 64 + cg + j4 * 4] =
                make_float4(acc[j4 * 4], acc[j4 * 4 + 1], acc[j4 * 4 + 2], acc[j4 * 4 + 3]);
    }
}

// ---------------- fold edge-embedding into message weights ----------------
// [h,e]@msgW = h@msgW[:64] + (ea@edgeW + edgeb)@msgW[64:96]
//   W'[k][c]     = msgW[k][c]                       k in [0,64)
//   W'[64+k2][c] = sum_j edgeW[k2][j]*msgW[64+j][c] k2 in [0,16)
//   b'[c]        = msgb[c] + sum_j edgeb[j]*msgW[64+j][c]
__global__ void fold_kernel(const float* __restrict__ msgW, const float* __restrict__ msgB,
                            const float* __restrict__ edgeW, const float* __restrict__ edgeB) {
    int l = blockIdx.x;
    int tid = threadIdx.x;  // 256
    const float* Wl = msgW + l * 96 * 64;
    for (int i = tid; i < 4096; i += 256) g_msgW[l][i] = Wl[i];
    for (int i = tid; i < 1024; i += 256) {
        int k2 = i >> 6, c = i & 63;
        float s = 0.f;
#pragma unroll 8
        for (int j = 0; j < 32; j++) s += edgeW[k2 * 32 + j] * Wl[(64 + j) * 64 + c];
        g_msgW[l][(64 + k2) * 64 + c] = s;
    }
    if (tid < 64) {
        float s = msgB[l * 64 + tid];
#pragma unroll 8
        for (int j = 0; j < 32; j++) s += edgeB[j] * Wl[(64 + j) * 64 + tid];
        g_msgB[l][tid] = s;
    }
}

// ---------------- fused message pass ----------------
// per edge: v = relu([h[src], ea] @ W' + b'); red-add v into g_agg[dst]; accumulate sum/sumsq
__global__ void __launch_bounds__(256) msg_kernel(const float* __restrict__ ea,
                                                  const int* __restrict__ src,
                                                  const int* __restrict__ dst,
                                                  int layer) {
    __shared__ float sW[80 * 64];      // 20480 B
    __shared__ float sIn[64 * 84];     // 21504 B, padded stride 84
    __shared__ int   s_src[64], s_dst[64];
    __shared__ float s_stat[128];
    int tid = threadIdx.x;
    int e0 = blockIdx.x * 64;

    if (tid < 64) { s_src[tid] = src[e0 + tid]; s_dst[tid] = dst[e0 + tid]; }
    if (tid < 128) s_stat[tid] = 0.f;
    const float* Wl = g_msgW[layer];
    for (int i = tid; i < 1280; i += 256) ((float4*)sW)[i] = ((const float4*)Wl)[i];
    __syncthreads();

    // gather inputs: 20 float4 per edge (16 of h[src], 4 of raw edge_attr[16])
    {
        int i = tid;
#pragma unroll
        for (int it = 0; it < 5; it++, i += 256) {
            int r = i / 20, p = i - r * 20;
            float4 v;
            if (p < 16) v = *(const float4*)&g_h[s_src[r] * 64 + (p << 2)];
            else        v = ((const float4*)ea)[((e0 + r) << 2) + (p - 16)];
            *(float4*)&sIn[r * 84 + (p << 2)] = v;
        }
    }
    __syncthreads();

    int r = tid >> 2, cg = (tid & 3) << 4;
    const float* bl = g_msgB[layer];
    float acc[16];
#pragma unroll
    for (int j = 0; j < 16; j++) acc[j] = bl[cg + j];
#pragma unroll 5
    for (int k = 0; k < 80; k++) {
        float a = sIn[r * 84 + k];
#pragma unroll
        for (int j4 = 0; j4 < 4; j4++) {
            float4 w = *(float4*)&sW[k * 64 + cg + (j4 << 2)];
            acc[j4 * 4 + 0] += a * w.x;
            acc[j4 * 4 + 1] += a * w.y;
            acc[j4 * 4 + 2] += a * w.z;
            acc[j4 * 4 + 3] += a * w.w;
        }
    }

    // relu + raw scatter (BN affine folded into the update kernel's agg load)
#pragma unroll
    for (int j = 0; j < 16; j++) acc[j] = fmaxf(acc[j], 0.f);
    float* aggp = &g_agg[s_dst[r] * 64 + cg];
#pragma unroll
    for (int j4 = 0; j4 < 4; j4++)
        red_add_v4(aggp + j4 * 4, acc[j4 * 4], acc[j4 * 4 + 1], acc[j4 * 4 + 2], acc[j4 * 4 + 3]);

    // BN stats: shfl-reduce over the 8 edge-rows in each warp, then smem, then global
    float sq[16];
#pragma unroll
    for (int j = 0; j < 16; j++) sq[j] = acc[j] * acc[j];
#pragma unroll
    for (int m = 4; m <= 16; m <<= 1) {
#pragma unroll
        for (int j = 0; j < 16; j++) {
            acc[j] += __shfl_xor_sync(0xffffffffu, acc[j], m);
            sq[j]  += __shfl_xor_sync(0xffffffffu, sq[j],  m);
        }
    }
    if ((tid & 31) < 4) {
#pragma unroll
        for (int j = 0; j < 16; j++) {
            atomicAdd(&s_stat[cg + j], acc[j]);
            atomicAdd(&s_stat[64 + cg + j], sq[j]);
        }
    }
    __syncthreads();
    if (tid < 128) atomicAdd(&g_stats[tid], s_stat[tid]);
}

// ---------------- fused update: u = relu([h, BN_affine(agg)] @ upd_W + b) ----------------
__global__ void __launch_bounds__(256) upd_kernel(const float* __restrict__ W,
                                                  const float* __restrict__ b,
                                                  const float* __restrict__ mgamma,
                                                  const float* __restrict__ mbeta) {
    extern __shared__ float dyn[];
    float* sW     = dyn;                // 128*64 = 8192
    float* sIn    = dyn + 8192;         // 64*132 = 8448 (padded stride 132)
    float* s_sa   = dyn + 16640;        // 64
    float* s_sc   = dyn + 16704;        // 64
    float* s_stat = dyn + 16768;        // 128
    int tid = threadIdx.x;
    int n0 = blockIdx.x * 64;

    if (tid < 64) {
        float mu  = g_stats[tid] * (1.f / N_EDGES);
        float var = g_stats[64 + tid] * (1.f / N_EDGES) - mu * mu;
        float a = mgamma[tid] * rsqrtf(var + EPS);
        s_sa[tid] = a;
        s_sc[tid] = mbeta[tid] - mu * a;
    }
    if (tid < 128) s_stat[tid] = 0.f;
    for (int i = tid; i < 2048; i += 256) ((float4*)sW)[i] = ((const float4*)W)[i];
    __syncthreads();

    // load concat(h, BN_affine(agg)): 32 float4 per node
    for (int i = tid; i < 2048; i += 256) {
        int r = i >> 5, p = i & 31;
        int node = n0 + r;
        float4 v = make_float4(0.f, 0.f, 0.f, 0.f);
        if (node < N_NODES) {
            if (p < 16) {
                v = *(const float4*)&g_h[node * 64 + (p << 2)];
            } else {
                int c = (p - 16) << 2;
                float4 raw = *(const float4*)&g_agg[node * 64 + c];
                float dg = (float)g_deg[node];
                v.x = s_sa[c + 0] * raw.x + dg * s_sc[c + 0];
                v.y = s_sa[c + 1] * raw.y + dg * s_sc[c + 1];
                v.z = s_sa[c + 2] * raw.z + dg * s_sc[c + 2];
                v.w = s_sa[c + 3] * raw.w + dg * s_sc[c + 3];
            }
        }
        *(float4*)&sIn[r * 132 + (p << 2)] = v;
    }
    __syncthreads();

    int r = tid >> 2, cg = (tid & 3) << 4;
    int node = n0 + r;
    bool valid = node < N_NODES;
    float acc[16];
#pragma unroll
    for (int j = 0; j < 16; j++) acc[j] = b[cg + j];
#pragma unroll 4
    for (int k = 0; k < 128; k++) {
        float a = sIn[r * 132 + k];
#pragma unroll
        for (int j4 = 0; j4 < 4; j4++) {
            float4 w = *(float4*)&sW[k * 64 + cg + (j4 << 2)];
            acc[j4 * 4 + 0] += a * w.x;
            acc[j4 * 4 + 1] += a * w.y;
            acc[j4 * 4 + 2] += a * w.z;
            acc[j4 * 4 + 3] += a * w.w;
        }
    }
#pragma unroll
    for (int j = 0; j < 16; j++) acc[j] = valid ? fmaxf(acc[j], 0.f) : 0.f;
    if (valid) {
#pragma unroll
        for (int j4 = 0; j4 < 4; j4++)
            *(float4*)&g_htmp[node * 64 + cg + j4 * 4] =
                make_float4(acc[j4 * 4], acc[j4 * 4 + 1], acc[j4 * 4 + 2], acc[j4 * 4 + 3]);
    }
    float sq[16];
#pragma unroll
    for (int j = 0; j < 16; j++) sq[j] = acc[j] * acc[j];
#pragma unroll
    for (int m = 4; m <= 16; m <<= 1) {
#pragma unroll
        for (int j = 0; j < 16; j++) {
            acc[j] += __shfl_xor_sync(0xffffffffu, acc[j], m);
            sq[j]  += __shfl_xor_sync(0xffffffffu, sq[j],  m);
        }
    }
    if ((tid & 31) < 4) {
#pragma unroll
        for (int j = 0; j < 16; j++) {
            atomicAdd(&s_stat[cg + j], acc[j]);
            atomicAdd(&s_stat[64 + cg + j], sq[j]);
        }
    }
    __syncthreads();
    if (tid < 128) atomicAdd(&g_stats[128 + tid], s_stat[tid]);
}

// ---------------- BN normalize update; last layer scatters into graph pool ----------------
__global__ void __launch_bounds__(256) norm_kernel(const float* __restrict__ ugamma,
                                                    const float* __restrict__ ubeta,
                                                    const int* __restrict__ batch,
                                                    int last) {
    __shared__ float s_a[64], s_c[64];
    int tid = threadIdx.x;
    if (tid < 64) {
        float mu  = g_stats[128 + tid] * (1.f / N_NODES);
        float var = g_stats[192 + tid] * (1.f / N_NODES) - mu * mu;
        float a = ugamma[tid] * rsqrtf(var + EPS);
        s_a[tid] = a;
        s_c[tid] = ubeta[tid] - mu * a;
    }
    __syncthreads();
    int i = blockIdx.x * 256 + tid;  // over N_NODES*16 float4 units
    if (i < N_NODES * 16) {
        int node = i >> 4, c = (i & 15) * 4;
        float4 v = *(const float4*)&g_htmp[node * 64 + c];
        float4 o;
        o.x = s_a[c + 0] * v.x + s_c[c + 0];
        o.y = s_a[c + 1] * v.y + s_c[c + 1];
        o.z = s_a[c + 2] * v.z + s_c[c + 2];
        o.w = s_a[c + 3] * v.w + s_c[c + 3];
        if (last) red_add_v4(&g_graph[batch[node] * 64 + c], o.x, o.y, o.z, o.w);
        else      *(float4*)&g_h[node * 64 + c] = o;
    }
}

// ---------------- readout: relu(g@r1_W + r1_b) @ r2_W + r2_b ----------------
__global__ void __launch_bounds__(64) readout_kernel(const float* __restrict__ r1W,
                                                     const float* __restrict__ r1b,
                                                     const float* __restrict__ r2W,
                                                     const float* __restrict__ r2b,
                                                     float* __restrict__ out) {
    __shared__ float sg[64];
    __shared__ float sp[2];
    int b = blockIdx.x, t = threadIdx.x;
    sg[t] = g_graph[b * 64 + t];
    __syncthreads();
    float acc = r1b[t];
#pragma unroll 8
    for (int k = 0; k < 64; k++) acc += sg[k] * r1W[k * 64 + t];
    float v = fmaxf(acc, 0.f) * r2W[t];
#pragma unroll
    for (int m = 16; m >= 1; m >>= 1) v += __shfl_xor_sync(0xffffffffu, v, m);
    if ((t & 31) == 0) sp[t >> 5] = v;
    __syncthreads();
    if (t == 0) out[b] = sp[0] + sp[1] + r2b[0];
}

// ---------------- launch ----------------
extern "C" void kernel_launch(void* const* d_in, const int* in_sizes, int n_in,
                              void* d_out, int out_size) {
    const float* x      = (const float*)d_in[0];
    const float* ea     = (const float*)d_in[1];
    const int*   eidx   = (const int*)d_in[2];
    const int*   batch  = (const int*)d_in[3];
    const float* nodeW  = (const float*)d_in[4];
    const float* nodeb  = (const float*)d_in[5];
    const float* edgeW  = (const float*)d_in[6];
    const float* edgeb  = (const float*)d_in[7];
    const float* msgW   = (const float*)d_in[8];
    const float* msgb   = (const float*)d_in[9];
    const float* mgamma = (const float*)d_in[10];
    const float* mbeta  = (const float*)d_in[11];
    const float* updW   = (const float*)d_in[12];
    const float* updb   = (const float*)d_in[13];
    const float* ugamma = (const float*)d_in[14];
    const float* ubeta  = (const float*)d_in[15];
    const float* r1W    = (const float*)d_in[16];
    const float* r1b    = (const float*)d_in[17];
    const float* r2W    = (const float*)d_in[18];
    const float* r2b    = (const float*)d_in[19];
    float* out = (float*)d_out;

    const int* src = eidx;
    const int* dst = eidx + N_EDGES;

    void *agg_p, *stats_p, *graph_p, *deg_p;
    cudaGetSymbolAddress(&agg_p, g_agg);
    cudaGetSymbolAddress(&stats_p, g_stats);
    cudaGetSymbolAddress(&graph_p, g_graph);
    cudaGetSymbolAddress(&deg_p, g_deg);

    const size_t UPD_SMEM = 16896 * sizeof(float);  // 67584 B
    cudaFuncSetAttribute(upd_kernel, cudaFuncAttributeMaxDynamicSharedMemorySize, (int)UPD_SMEM);

    cudaMemsetAsync(deg_p, 0, N_NODES * sizeof(int));
    cudaMemsetAsync(graph_p, 0, NUM_GRAPHS * HID * sizeof(float));

    deg_kernel<<<(N_EDGES + 255) / 256, 256>>>(dst);
    node_embed_kernel<<<(N_NODES + 63) / 64, 256>>>(x, nodeW, nodeb);
    fold_kernel<<<3, 256>>>(msgW, msgb, edgeW, edgeb);

    for (int l = 0; l < 3; l++) {
        cudaMemsetAsync(agg_p, 0, (size_t)N_NODES * HID * sizeof(float));
        cudaMemsetAsync(stats_p, 0, 256 * sizeof(float));
        msg_kernel<<<N_EDGES / 64, 256>>>(ea, src, dst, l);
        upd_kernel<<<(N_NODES + 63) / 64, 256, UPD_SMEM>>>(updW + l * 128 * 64, updb + l * 64,
                                                           mgamma + l * 64, mbeta + l * 64);
        norm_kernel<<<(N_NODES * 16 + 255) / 256, 256>>>(ugamma + l * 64, ubeta + l * 64,
                                                         batch, l == 2);
    }
    readout_kernel<<<NUM_GRAPHS, 64>>>(r1W, r1b, r2W, r2b, out);
    (void)in_sizes; (void)n_in; (void)out_size;
}

// round 11
// speedup vs baseline: 2.4924x; 2.4924x over previous
#include <cuda_runtime.h>

#define N_NODES   100000
#define N_EDGES   1600000
#define NUM_GRAPHS 1000
#define HID 64
#define EPS 1e-5f

// ---------------- device scratch ----------------
__device__ float g_h[N_NODES * HID];
__device__ float g_htmp[N_NODES * HID];
__device__ float g_agg[N_NODES * HID];
__device__ float g_graph[NUM_GRAPHS * HID];
__device__ int   g_deg[N_NODES];
__device__ float g_msgW[3][80 * 64];
__device__ float g_msgB[3][64];
__device__ float g_stats[256];

__device__ __forceinline__ void red_add_v4(float* p, float a, float b, float c, float d) {
    asm volatile("red.global.add.v4.f32 [%0], {%1,%2,%3,%4};"
                 :: "l"(p), "f"(a), "f"(b), "f"(c), "f"(d) : "memory");
}

// ---------------- in-degree ----------------
__global__ void deg_kernel(const int* __restrict__ dst) {
    int i = blockIdx.x * blockDim.x + threadIdx.x;
    if (i < N_EDGES) atomicAdd(&g_deg[dst[i]], 1);
}

// ---------------- node embedding: h = x @ node_W + node_b ----------------
__global__ void __launch_bounds__(256) node_embed_kernel(const float* __restrict__ x,
                                                         const float* __restrict__ W,
                                                         const float* __restrict__ b) {
    __shared__ float sW[32 * 64];
    __shared__ float sIn[64 * 36];
    int tid = threadIdx.x;
    int n0 = blockIdx.x * 64;

    for (int i = tid; i < 512; i += 256) ((float4*)sW)[i] = ((const float4*)W)[i];
    for (int i = tid; i < 512; i += 256) {
        int r = i >> 3, p = i & 7;
        int node = n0 + r;
        float4 v = make_float4(0.f, 0.f, 0.f, 0.f);
        if (node < N_NODES) v = ((const float4*)x)[node * 8 + p];
        *(float4*)&sIn[r * 36 + p * 4] = v;
    }
    __syncthreads();

    int r = tid >> 2, cg = (tid & 3) << 4, rot = tid & 3;
    int pj[4];
#pragma unroll
    for (int i4 = 0; i4 < 4; i4++) pj[i4] = ((i4 + rot) & 3) << 2;

    float acc[16];
#pragma unroll
    for (int i4 = 0; i4 < 4; i4++)
#pragma unroll
        for (int jj = 0; jj < 4; jj++) acc[i4 * 4 + jj] = b[cg + pj[i4] + jj];
#pragma unroll 8
    for (int k = 0; k < 32; k++) {
        float a = sIn[r * 36 + k];
#pragma unroll
        for (int i4 = 0; i4 < 4; i4++) {
            float4 w = *(float4*)&sW[k * 64 + cg + pj[i4]];
            acc[i4 * 4 + 0] += a * w.x;
            acc[i4 * 4 + 1] += a * w.y;
            acc[i4 * 4 + 2] += a * w.z;
            acc[i4 * 4 + 3] += a * w.w;
        }
    }
    int node = n0 + r;
    if (node < N_NODES) {
#pragma unroll
        for (int i4 = 0; i4 < 4; i4++)
            *(float4*)&g_h[node * 64 + cg + pj[i4]] =
                make_float4(acc[i4 * 4], acc[i4 * 4 + 1], acc[i4 * 4 + 2], acc[i4 * 4 + 3]);
    }
}

// ---------------- fold edge-embedding into message weights ----------------
__global__ void fold_kernel(const float* __restrict__ msgW, const float* __restrict__ msgB,
                            const float* __restrict__ edgeW, const float* __restrict__ edgeB) {
    int l = blockIdx.x;
    int tid = threadIdx.x;  // 256
    const float* Wl = msgW + l * 96 * 64;
    for (int i = tid; i < 4096; i += 256) g_msgW[l][i] = Wl[i];
    for (int i = tid; i < 1024; i += 256) {
        int k2 = i >> 6, c = i & 63;
        float s = 0.f;
#pragma unroll 8
        for (int j = 0; j < 32; j++) s += edgeW[k2 * 32 + j] * Wl[(64 + j) * 64 + c];
        g_msgW[l][(64 + k2) * 64 + c] = s;
    }
    if (tid < 64) {
        float s = msgB[l * 64 + tid];
#pragma unroll 8
        for (int j = 0; j < 32; j++) s += edgeB[j] * Wl[(64 + j) * 64 + tid];
        g_msgB[l][tid] = s;
    }
}

// ---------------- fused message pass: 128 edges/block, 2 edges/thread ----------------
__global__ void __launch_bounds__(256) msg_kernel(const float* __restrict__ ea,
                                                  const int* __restrict__ src,
                                                  const int* __restrict__ dst,
                                                  int layer) {
    extern __shared__ float dyn[];
    float* sW     = dyn;                    // 80*64 = 5120 floats
    float* sIn    = dyn + 5120;             // 128*84 = 10752 floats
    float* s_stat = dyn + 15872;            // 128 floats
    int*   s_src  = (int*)(dyn + 16000);    // 128 ints
    int*   s_dst  = (int*)(dyn + 16128);    // 128 ints
    int tid = threadIdx.x;
    int e0 = blockIdx.x * 128;

    if (tid < 128) {
        s_src[tid] = src[e0 + tid];
        s_dst[tid] = dst[e0 + tid];
        s_stat[tid] = 0.f;
    }
    const float* Wl = g_msgW[layer];
    for (int i = tid; i < 1280; i += 256) ((float4*)sW)[i] = ((const float4*)Wl)[i];
    __syncthreads();

    // gather: 128 edges x 20 float4 (16 of h[src], 4 of edge_attr)
#pragma unroll
    for (int it = 0; it < 10; it++) {
        int i = tid + it * 256;
        int r = i / 20, p = i - r * 20;
        float4 v;
        if (p < 16) v = *(const float4*)&g_h[s_src[r] * 64 + (p << 2)];
        else        v = ((const float4*)ea)[((e0 + r) << 2) + (p - 16)];
        *(float4*)&sIn[r * 84 + (p << 2)] = v;
    }
    __syncthreads();

    int r = tid >> 2, cg = (tid & 3) << 4, rot = tid & 3;
    int pj[4];
#pragma unroll
    for (int i4 = 0; i4 < 4; i4++) pj[i4] = ((i4 + rot) & 3) << 2;

    const float* bl = g_msgB[layer];
    float acc0[16], acc1[16];
#pragma unroll
    for (int i4 = 0; i4 < 4; i4++)
#pragma unroll
        for (int jj = 0; jj < 4; jj++) {
            float bb = bl[cg + pj[i4] + jj];
            acc0[i4 * 4 + jj] = bb;
            acc1[i4 * 4 + jj] = bb;
        }

    const float* in0 = &sIn[r * 84];
    const float* in1 = &sIn[(r + 64) * 84];
#pragma unroll 5
    for (int k = 0; k < 80; k++) {
        float a0 = in0[k], a1 = in1[k];
#pragma unroll
        for (int i4 = 0; i4 < 4; i4++) {
            float4 w = *(float4*)&sW[k * 64 + cg + pj[i4]];
            acc0[i4 * 4 + 0] += a0 * w.x; acc0[i4 * 4 + 1] += a0 * w.y;
            acc0[i4 * 4 + 2] += a0 * w.z; acc0[i4 * 4 + 3] += a0 * w.w;
            acc1[i4 * 4 + 0] += a1 * w.x; acc1[i4 * 4 + 1] += a1 * w.y;
            acc1[i4 * 4 + 2] += a1 * w.z; acc1[i4 * 4 + 3] += a1 * w.w;
        }
    }

#pragma unroll
    for (int j = 0; j < 16; j++) {
        acc0[j] = fmaxf(acc0[j], 0.f);
        acc1[j] = fmaxf(acc1[j], 0.f);
    }
    float* p0 = &g_agg[s_dst[r] * 64 + cg];
    float* p1 = &g_agg[s_dst[r + 64] * 64 + cg];
#pragma unroll
    for (int i4 = 0; i4 < 4; i4++) {
        red_add_v4(p0 + pj[i4], acc0[i4 * 4], acc0[i4 * 4 + 1], acc0[i4 * 4 + 2], acc0[i4 * 4 + 3]);
        red_add_v4(p1 + pj[i4], acc1[i4 * 4], acc1[i4 * 4 + 1], acc1[i4 * 4 + 2], acc1[i4 * 4 + 3]);
    }

    // BN stats over both edges, then shuffle-reduce over 8 slots (16 edges) per warp
    float s[16], sq[16];
#pragma unroll
    for (int j = 0; j < 16; j++) {
        s[j]  = acc0[j] + acc1[j];
        sq[j] = acc0[j] * acc0[j] + acc1[j] * acc1[j];
    }
#pragma unroll
    for (int m = 4; m <= 16; m <<= 1) {
#pragma unroll
        for (int j = 0; j < 16; j++) {
            s[j]  += __shfl_xor_sync(0xffffffffu, s[j],  m);
            sq[j] += __shfl_xor_sync(0xffffffffu, sq[j], m);
        }
    }
    if ((tid & 31) < 4) {
#pragma unroll
        for (int i4 = 0; i4 < 4; i4++)
#pragma unroll
            for (int jj = 0; jj < 4; jj++) {
                atomicAdd(&s_stat[cg + pj[i4] + jj], s[i4 * 4 + jj]);
                atomicAdd(&s_stat[64 + cg + pj[i4] + jj], sq[i4 * 4 + jj]);
            }
    }
    __syncthreads();
    if (tid < 128) atomicAdd(&g_stats[tid], s_stat[tid]);
}

// ---------------- fused update: u = relu([h, BN_affine(agg)] @ upd_W + b) ----------------
__global__ void __launch_bounds__(256) upd_kernel(const float* __restrict__ W,
                                                  const float* __restrict__ b,
                                                  const float* __restrict__ mgamma,
                                                  const float* __restrict__ mbeta) {
    extern __shared__ float dyn[];
    float* sW     = dyn;                // 128*64 = 8192
    float* sIn    = dyn + 8192;         // 64*132 = 8448
    float* s_sa   = dyn + 16640;        // 64
    float* s_sc   = dyn + 16704;        // 64
    float* s_stat = dyn + 16768;        // 128
    int tid = threadIdx.x;
    int n0 = blockIdx.x * 64;

    if (tid < 64) {
        float mu  = g_stats[tid] * (1.f / N_EDGES);
        float var = g_stats[64 + tid] * (1.f / N_EDGES) - mu * mu;
        float a = mgamma[tid] * rsqrtf(var + EPS);
        s_sa[tid] = a;
        s_sc[tid] = mbeta[tid] - mu * a;
    }
    if (tid < 128) s_stat[tid] = 0.f;
    for (int i = tid; i < 2048; i += 256) ((float4*)sW)[i] = ((const float4*)W)[i];
    __syncthreads();

    for (int i = tid; i < 2048; i += 256) {
        int r = i >> 5, p = i & 31;
        int node = n0 + r;
        float4 v = make_float4(0.f, 0.f, 0.f, 0.f);
        if (node < N_NODES) {
            if (p < 16) {
                v = *(const float4*)&g_h[node * 64 + (p << 2)];
            } else {
                int c = (p - 16) << 2;
                float4 raw = *(const float4*)&g_agg[node * 64 + c];
                float dg = (float)g_deg[node];
                v.x = s_sa[c + 0] * raw.x + dg * s_sc[c + 0];
                v.y = s_sa[c + 1] * raw.y + dg * s_sc[c + 1];
                v.z = s_sa[c + 2] * raw.z + dg * s_sc[c + 2];
                v.w = s_sa[c + 3] * raw.w + dg * s_sc[c + 3];
            }
        }
        *(float4*)&sIn[r * 132 + (p << 2)] = v;
    }
    __syncthreads();

    int r = tid >> 2, cg = (tid & 3) << 4, rot = tid & 3;
    int pj[4];
#pragma unroll
    for (int i4 = 0; i4 < 4; i4++) pj[i4] = ((i4 + rot) & 3) << 2;

    int node = n0 + r;
    bool valid = node < N_NODES;
    float acc[16];
#pragma unroll
    for (int i4 = 0; i4 < 4; i4++)
#pragma unroll
        for (int jj = 0; jj < 4; jj++) acc[i4 * 4 + jj] = b[cg + pj[i4] + jj];
#pragma unroll 4
    for (int k = 0; k < 128; k++) {
        float a = sIn[r * 132 + k];
#pragma unroll
        for (int i4 = 0; i4 < 4; i4++) {
            float4 w = *(float4*)&sW[k * 64 + cg + pj[i4]];
            acc[i4 * 4 + 0] += a * w.x;
            acc[i4 * 4 + 1] += a * w.y;
            acc[i4 * 4 + 2] += a * w.z;
            acc[i4 * 4 + 3] += a * w.w;
        }
    }
#pragma unroll
    for (int j = 0; j < 16; j++) acc[j] = valid ? fmaxf(acc[j], 0.f) : 0.f;
    if (valid) {
#pragma unroll
        for (int i4 = 0; i4 < 4; i4++)
            *(float4*)&g_htmp[node * 64 + cg + pj[i4]] =
                make_float4(acc[i4 * 4], acc[i4 * 4 + 1], acc[i4 * 4 + 2], acc[i4 * 4 + 3]);
    }
    float sq[16];
#pragma unroll
    for (int j = 0; j < 16; j++) sq[j] = acc[j] * acc[j];
#pragma unroll
    for (int m = 4; m <= 16; m <<= 1) {
#pragma unroll
        for (int j = 0; j < 16; j++) {
            acc[j] += __shfl_xor_sync(0xffffffffu, acc[j], m);
            sq[j]  += __shfl_xor_sync(0xffffffffu, sq[j],  m);
        }
    }
    if ((tid & 31) < 4) {
#pragma unroll
        for (int i4 = 0; i4 < 4; i4++)
#pragma unroll
            for (int jj = 0; jj < 4; jj++) {
                atomicAdd(&s_stat[cg + pj[i4] + jj], acc[i4 * 4 + jj]);
                atomicAdd(&s_stat[64 + cg + pj[i4] + jj], sq[i4 * 4 + jj]);
            }
    }
    __syncthreads();
    if (tid < 128) atomicAdd(&g_stats[128 + tid], s_stat[tid]);
}

// ---------------- BN normalize update; last layer scatters into graph pool ----------------
__global__ void __launch_bounds__(256) norm_kernel(const float* __restrict__ ugamma,
                                                    const float* __restrict__ ubeta,
                                                    const int* __restrict__ batch,
                                                    int last) {
    __shared__ float s_a[64], s_c[64];
    int tid = threadIdx.x;
    if (tid < 64) {
        float mu  = g_stats[128 + tid] * (1.f / N_NODES);
        float var = g_stats[192 + tid] * (1.f / N_NODES) - mu * mu;
        float a = ugamma[tid] * rsqrtf(var + EPS);
        s_a[tid] = a;
        s_c[tid] = ubeta[tid] - mu * a;
    }
    __syncthreads();
    int i = blockIdx.x * 256 + tid;
    if (i < N_NODES * 16) {
        int node = i >> 4, c = (i & 15) * 4;
        float4 v = *(const float4*)&g_htmp[node * 64 + c];
        float4 o;
        o.x = s_a[c + 0] * v.x + s_c[c + 0];
        o.y = s_a[c + 1] * v.y + s_c[c + 1];
        o.z = s_a[c + 2] * v.z + s_c[c + 2];
        o.w = s_a[c + 3] * v.w + s_c[c + 3];
        if (last) red_add_v4(&g_graph[batch[node] * 64 + c], o.x, o.y, o.z, o.w);
        else      *(float4*)&g_h[node * 64 + c] = o;
    }
}

// ---------------- readout ----------------
__global__ void __launch_bounds__(64) readout_kernel(const float* __restrict__ r1W,
                                                     const float* __restrict__ r1b,
                                                     const float* __restrict__ r2W,
                                                     const float* __restrict__ r2b,
                                                     float* __restrict__ out) {
    __shared__ float sg[64];
    __shared__ float sp[2];
    int b = blockIdx.x, t = threadIdx.x;
    sg[t] = g_graph[b * 64 + t];
    __syncthreads();
    float acc = r1b[t];
#pragma unroll 8
    for (int k = 0; k < 64; k++) acc += sg[k] * r1W[k * 64 + t];
    float v = fmaxf(acc, 0.f) * r2W[t];
#pragma unroll
    for (int m = 16; m >= 1; m >>= 1) v += __shfl_xor_sync(0xffffffffu, v, m);
    if ((t & 31) == 0) sp[t >> 5] = v;
    __syncthreads();
    if (t == 0) out[b] = sp[0] + sp[1] + r2b[0];
}

// ---------------- launch ----------------
extern "C" void kernel_launch(void* const* d_in, const int* in_sizes, int n_in,
                              void* d_out, int out_size) {
    const float* x      = (const float*)d_in[0];
    const float* ea     = (const float*)d_in[1];
    const int*   eidx   = (const int*)d_in[2];
    const int*   batch  = (const int*)d_in[3];
    const float* nodeW  = (const float*)d_in[4];
    const float* nodeb  = (const float*)d_in[5];
    const float* edgeW  = (const float*)d_in[6];
    const float* edgeb  = (const float*)d_in[7];
    const float* msgW   = (const float*)d_in[8];
    const float* msgb   = (const float*)d_in[9];
    const float* mgamma = (const float*)d_in[10];
    const float* mbeta  = (const float*)d_in[11];
    const float* updW   = (const float*)d_in[12];
    const float* updb   = (const float*)d_in[13];
    const float* ugamma = (const float*)d_in[14];
    const float* ubeta  = (const float*)d_in[15];
    const float* r1W    = (const float*)d_in[16];
    const float* r1b    = (const float*)d_in[17];
    const float* r2W    = (const float*)d_in[18];
    const float* r2b    = (const float*)d_in[19];
    float* out = (float*)d_out;

    const int* src = eidx;
    const int* dst = eidx + N_EDGES;

    void *agg_p, *stats_p, *graph_p, *deg_p;
    cudaGetSymbolAddress(&agg_p, g_agg);
    cudaGetSymbolAddress(&stats_p, g_stats);
    cudaGetSymbolAddress(&graph_p, g_graph);
    cudaGetSymbolAddress(&deg_p, g_deg);

    const size_t MSG_SMEM = 16256 * sizeof(float);  // 65024 B
    const size_t UPD_SMEM = 16896 * sizeof(float);  // 67584 B
    cudaFuncSetAttribute(msg_kernel, cudaFuncAttributeMaxDynamicSharedMemorySize, (int)MSG_SMEM);
    cudaFuncSetAttribute(upd_kernel, cudaFuncAttributeMaxDynamicSharedMemorySize, (int)UPD_SMEM);

    cudaMemsetAsync(deg_p, 0, N_NODES * sizeof(int));
    cudaMemsetAsync(graph_p, 0, NUM_GRAPHS * HID * sizeof(float));

    deg_kernel<<<(N_EDGES + 255) / 256, 256>>>(dst);
    node_embed_kernel<<<(N_NODES + 63) / 64, 256>>>(x, nodeW, nodeb);
    fold_kernel<<<3, 256>>>(msgW, msgb, edgeW, edgeb);

    for (int l = 0; l < 3; l++) {
        cudaMemsetAsync(agg_p, 0, (size_t)N_NODES * HID * sizeof(float));
        cudaMemsetAsync(stats_p, 0, 256 * sizeof(float));
        msg_kernel<<<N_EDGES / 128, 256, MSG_SMEM>>>(ea, src, dst, l);
        upd_kernel<<<(N_NODES + 63) / 64, 256, UPD_SMEM>>>(updW + l * 128 * 64, updb + l * 64,
                                                           mgamma + l * 64, mbeta + l * 64);
        norm_kernel<<<(N_NODES * 16 + 255) / 256, 256>>>(ugamma + l * 64, ubeta + l * 64,
                                                         batch, l == 2);
    }
    readout_kernel<<<NUM_GRAPHS, 64>>>(r1W, r1b, r2W, r2b, out);
    (void)in_sizes; (void)n_in; (void)out_size;
}